// round 11
// baseline (speedup 1.0000x reference)
#include <cuda_runtime.h>
#include <cuda_fp16.h>
#include <cstdint>

// MX (block-32, E8M0 scale, E4M3 elements) quantize-dequantize using the
// HARDWARE E4M3 converter: cvt.rn.satfinite.e4m3x2.f32 does RNE-to-3-bits,
// saturation at 448, and E4M3 subnormals — exactly the reference semantics —
// in one op per element pair. Scales are exact powers of two built from the
// block-amax exponent byte, so the pre/post multiplies are exact.
// VPT=4 float4 per thread; warp covers 128 contiguous floats = 4 MX blocks
// (8 adjacent lanes each). All 4 block-amax exponent bytes packed into ONE
// u32, reduced with 3 x (shfl_xor + vmaxu4).

#define VPT 4

__device__ __forceinline__ float2 qdq2(float a, float b, float inv_scale, float scale) {
    // scale to MX domain (exact power-of-two multiply)
    float sa = a * inv_scale;
    float sb = b * inv_scale;
    // HW E4M3 quantize (RNE, satfinite, subnormals) then exact widen back
    unsigned short q;
    asm("cvt.rn.satfinite.e4m3x2.f32 %0, %1, %2;" : "=h"(q) : "f"(sb), "f"(sa));
    unsigned hh;
    asm("cvt.rn.f16x2.e4m3x2 %0, %1;" : "=r"(hh) : "h"(q));
    __half2 h2 = *reinterpret_cast<__half2*>(&hh);
    float2 f = __half22float2(h2);          // exact
    f.x *= scale;                            // exact power-of-two multiply
    f.y *= scale;
    return f;
}

template <bool EXACT>
__global__ void __launch_bounds__(256) mx_qdq_kernel(const float4* __restrict__ in,
                                                     float4* __restrict__ out,
                                                     int n4) {
    int base = blockIdx.x * (256 * VPT) + threadIdx.x;

    // ---- front-batched streaming loads (MLP = 4) ----
    float4 v[VPT];
#pragma unroll
    for (int j = 0; j < VPT; j++) {
        int idx = base + j * 256;
        if (EXACT || idx < n4) v[j] = __ldcs(&in[idx]);
    }

    // ---- per-chunk abs-bit max -> exponent byte, packed 4-per-u32 ----
    unsigned p = 0u;
#pragma unroll
    for (int j = 0; j < VPT; j++) {
        unsigned a = max(max(__float_as_uint(v[j].x) & 0x7FFFFFFFu,
                             __float_as_uint(v[j].y) & 0x7FFFFFFFu),
                         max(__float_as_uint(v[j].z) & 0x7FFFFFFFu,
                             __float_as_uint(v[j].w) & 0x7FFFFFFFu));
        if (!EXACT && (base + j * 256) >= n4) a = 0u;
        p |= (a >> 23) << (8 * j);
    }

    // ---- 8-lane group reduction, byte-wise max (block = 8 adjacent lanes) ----
#pragma unroll
    for (int m = 1; m <= 4; m <<= 1)
        p = __vmaxu4(p, __shfl_xor_sync(0xFFFFFFFFu, p, m));

    // ---- HW-cvt quantize-dequantize + streaming store ----
#pragma unroll
    for (int j = 0; j < VPT; j++) {
        int idx = base + j * 256;
        if (!EXACT && idx >= n4) continue;

        // se = clip(floor(log2(amax)) - 8, -127, 127); E8M0 low clip via max(E,8).
        // Exponent-field read is exact for normal amax; subnormal/zero amax
        // clamps to se=-127 (all-zero block outputs zeros under any scale).
        unsigned mE = max((p >> (8 * j)) & 0xFFu, 8u);
        float inv_scale = __uint_as_float((262u - mE) << 23);            // 2^-se, always normal
        float scale = (mE > 8u) ? __uint_as_float((mE - 8u) << 23)       // 2^se
                                : __uint_as_float(0x00400000u);          // 2^-127 (subnormal)

        float4 u = v[j], o;
        float2 lo = qdq2(u.x, u.y, inv_scale, scale);
        float2 hi = qdq2(u.z, u.w, inv_scale, scale);
        o.x = lo.x; o.y = lo.y; o.z = hi.x; o.w = hi.y;
        __stcs(&out[idx], o);
    }
}

extern "C" void kernel_launch(void* const* d_in, const int* in_sizes, int n_in,
                              void* d_out, int out_size) {
    const float4* x = (const float4*)d_in[0];
    float4* out = (float4*)d_out;
    int n = in_sizes[0];            // 4096*8192
    int n4 = n / 4;
    const int per_block = 256 * VPT;
    if (n4 % per_block == 0) {
        mx_qdq_kernel<true><<<n4 / per_block, 256>>>(x, out, n4);
    } else {
        mx_qdq_kernel<false><<<(n4 + per_block - 1) / per_block, 256>>>(x, out, n4);
    }
}